// round 12
// baseline (speedup 1.0000x reference)
#include <cuda_runtime.h>
#include <math.h>

#define NRES  16384
#define NODES 49152
#define NODESP (NODES + 32)   // sentinel padding region
#define NEDGE 786432
#define EMB   128
#define NRAD  64
#define TRES  16
#define STRF  36   // activation column stride in floats
#define STRD  18   // in u64
#define STRV  9    // in ulonglong2

typedef unsigned long long u64;

__device__ __forceinline__ u64 pk2(float lo, float hi) {
    u64 r; asm("mov.b64 %0,{%1,%2};" : "=l"(r) : "f"(lo), "f"(hi)); return r;
}
__device__ __forceinline__ u64 pkw(float w) {
    u64 r; asm("mov.b64 %0,{%1,%1};" : "=l"(r) : "f"(w)); return r;
}
__device__ __forceinline__ void up2(u64 a, float& lo, float& hi) {
    asm("mov.b64 {%0,%1},%2;" : "=f"(lo), "=f"(hi) : "l"(a));
}
__device__ __forceinline__ u64 ff2(u64 a, u64 b, u64 c) {
    u64 d; asm("fma.rn.f32x2 %0,%1,%2,%3;" : "=l"(d) : "l"(a), "l"(b), "l"(c)); return d;
}
__device__ __forceinline__ float fast_silu(float t) {
    float h = 0.5f * t, th;
    asm("tanh.approx.f32 %0,%1;" : "=f"(th) : "f"(h));
    return fmaf(h, th, h);
}

// ---------------- device scratch ----------------
// INVARIANT: g_accR is all-zero at kernel_launch entry. Statically zero-init on
// load; k_clean (last launch) re-zeroes exactly the rows dirtied this call.
__device__ float4 g_pos[NODES];
__device__ float  g_accR[(size_t)NODESP * 3 * NRAD];
__device__ float  g_cnt[NODESP * 3];
__device__ float  g_lig[(size_t)NODESP * EMB];
__device__ float  g_bp[3 * EMB];
__device__ float  g_Wp[192 * EMB];
__device__ int    g_ndirty[NODES];
__device__ int    g_dlist[NODES + 64];
__device__ int    g_dcnt;

// ---------------- init: small arrays + weight prep (accR zero is lazy now) ----------------
__global__ void __launch_bounds__(256) k_init(const float* __restrict__ pn,
                                              const float* __restrict__ pca,
                                              const float* __restrict__ pc,
                                              const float* __restrict__ ligW,
                                              const float* __restrict__ ligb,
                                              const float* __restrict__ bbemb) {
    int idx = blockIdx.x * blockDim.x + threadIdx.x;
    int stride = gridDim.x * blockDim.x;
    const int n2 = (NODESP * 3) / 4;
    float4 z = make_float4(0.f, 0.f, 0.f, 0.f);
    float4* cvec = reinterpret_cast<float4*>(g_cnt);
    for (int i = idx; i < n2; i += stride) cvec[i] = z;
    for (int i = idx; i < NODES; i += stride) g_ndirty[i] = 0;
    for (int i = idx; i < NODES + 64; i += stride) g_dlist[i] = NODES;  // sentinel
    if (idx == 0) g_dcnt = 0;

    if (idx < NRES) {
        int n = idx;
        g_pos[3 * n + 0] = make_float4(pn[3 * n], pn[3 * n + 1], pn[3 * n + 2], 0.f);
        g_pos[3 * n + 1] = make_float4(pca[3 * n], pca[3 * n + 1], pca[3 * n + 2], 0.f);
        g_pos[3 * n + 2] = make_float4(pc[3 * n], pc[3 * n + 1], pc[3 * n + 2], 0.f);
    }
    if (idx < 192 * EMB) {
        int c = idx & 127;
        int kk = idx >> 7;
        int t = kk / NRAD;
        int k = kk - t * NRAD;
        g_Wp[idx] = ligW[k * EMB + c] * bbemb[t * EMB + c];
    }
    if (idx < 3 * EMB) g_bp[idx] = ligb[idx & 127] * bbemb[idx];
}

// ---------------- edge phase: cutoff + claim-and-append compaction ----------------
__global__ void __launch_bounds__(256) k_edge(const int* __restrict__ ei) {
    int e = blockIdx.x * blockDim.x + threadIdx.x;
    if (e >= NEDGE) return;
    int i = ei[e];
    int j = ei[NEDGE + e];
    float4 pi = g_pos[i];
    float4 pj = g_pos[j];
    float dx = pi.x - pj.x, dy = pi.y - pj.y, dz = pi.z - pj.z;
    float d2 = dx * dx + dy * dy + dz * dz;
    int tj = j % 3;
    atomicAdd(&g_cnt[i * 3 + tj], 1.0f);
    if (d2 < 44.0f) {
        if (atomicExch(&g_ndirty[i], 1) == 0) {
            int p = atomicAdd(&g_dcnt, 1);
            g_dlist[p] = i;
        }
        float d = sqrtf(d2);
        float* base = &g_accR[(size_t)(i * 3 + tj) * NRAD];
        const float step = 5.0f / 63.0f;
#pragma unroll
        for (int k = 0; k < NRAD; k += 4) {
            float t0 = d - (k + 0) * step;
            float t1 = d - (k + 1) * step;
            float t2 = d - (k + 2) * step;
            float t3 = d - (k + 3) * step;
            float v0 = __expf(-10.0f * t0 * t0);
            float v1 = __expf(-10.0f * t1 * t1);
            float v2 = __expf(-10.0f * t2 * t2);
            float v3 = __expf(-10.0f * t3 * t3);
            unsigned long long gaddr = (unsigned long long)__cvta_generic_to_global(base + k);
            asm volatile("red.global.add.v4.f32 [%0], {%1,%2,%3,%4};"
                         :: "l"(gaddr), "f"(v0), "f"(v1), "f"(v2), "f"(v3) : "memory");
        }
    }
}

// ---------------- closed-form lig for ALL nodes (bandwidth-bound) ----------------
__global__ void __launch_bounds__(256) k_lig_all(const float* __restrict__ bbemb) {
    int idx = blockIdx.x * blockDim.x + threadIdx.x;   // NODES*64 slots
    int n = idx >> 6;
    int e0 = 2 * (idx & 63);
    if (n >= NODES) return;
    float c0 = g_cnt[n * 3 + 0], c1 = g_cnt[n * 3 + 1], c2 = g_cnt[n * 3 + 2];
    float deg = c0 + c1 + c2;
    int a = n % 3;
    float2 xs = *reinterpret_cast<const float2*>(bbemb + a * EMB + e0);
    float2 b0 = *reinterpret_cast<const float2*>(g_bp + e0);
    float2 b1 = *reinterpret_cast<const float2*>(g_bp + EMB + e0);
    float2 b2 = *reinterpret_cast<const float2*>(g_bp + 2 * EMB + e0);
    float2 r;
    r.x = deg * xs.x + c0 * b0.x + c1 * b1.x + c2 * b2.x;
    r.y = deg * xs.y + c0 * b0.y + c1 * b1.y + c2 * b2.y;
    *reinterpret_cast<float2*>(g_lig + (size_t)n * EMB + e0) = r;
}

// ---------------- FMA2 GEMM: 4 row-pairs, adjacent channel pair (e0, e0+1) ----------------
template<int K, bool ACC>
__device__ __forceinline__ void gemm4(const ulonglong2* __restrict__ X, int q,
                                      const float* __restrict__ W, int ldw,
                                      int e0, u64* aA, u64* aB) {
    if (!ACC) {
#pragma unroll
        for (int i = 0; i < 4; i++) { aA[i] = 0ull; aB[i] = 0ull; }
    }
    const ulonglong2* xp = X + 2 * q;
#pragma unroll 4
    for (int k = 0; k < K; k++) {
        float2 wv = __ldg(reinterpret_cast<const float2*>(W + (size_t)k * ldw + e0));
        u64 w0 = pkw(wv.x);
        u64 w1 = pkw(wv.y);
        ulonglong2 x0 = xp[k * STRV + 0];
        ulonglong2 x1 = xp[k * STRV + 1];
        aA[0] = ff2(x0.x, w0, aA[0]); aA[1] = ff2(x0.y, w0, aA[1]);
        aA[2] = ff2(x1.x, w0, aA[2]); aA[3] = ff2(x1.y, w0, aA[3]);
        aB[0] = ff2(x0.x, w1, aB[0]); aB[1] = ff2(x0.y, w1, aB[1]);
        aB[2] = ff2(x1.x, w1, aB[2]); aB[3] = ff2(x1.y, w1, aB[3]);
    }
}

// ---------------- GEMM correction for dirty nodes only ----------------
__global__ void __launch_bounds__(256, 4) k_lig_fix() {
    __shared__ __align__(16) float shT[192 * STRF];
    __shared__ int shn[32];
    int tid = threadIdx.x;
    int i0 = blockIdx.x * 32;
    if (i0 >= g_dcnt) return;   // uniform per block

    if (tid < 32) shn[tid] = g_dlist[i0 + tid];
    __syncthreads();

    for (int q2 = tid; q2 < 1536; q2 += 256) {
        int r = q2 / 48, k4 = q2 - 48 * r;
        float4 v = *reinterpret_cast<const float4*>(g_accR + (size_t)shn[r] * 192 + k4 * 4);
        int kb = 4 * k4;
        shT[(kb + 0) * STRF + r] = v.x;
        shT[(kb + 1) * STRF + r] = v.y;
        shT[(kb + 2) * STRF + r] = v.z;
        shT[(kb + 3) * STRF + r] = v.w;
    }
    __syncthreads();

    int e0 = 2 * (tid & 63), q = tid >> 6;
    u64 aA[4], aB[4];
    gemm4<192, false>((const ulonglong2*)shT, q, g_Wp, 128, e0, aA, aB);

#pragma unroll
    for (int jj = 0; jj < 4; jj++) {
        int rp = 4 * q + jj;
        int v0 = shn[2 * rp], v1 = shn[2 * rp + 1];
        float ya0, ya1, yb0, yb1;
        up2(aA[jj], ya0, ya1);
        up2(aB[jj], yb0, yb1);
        float2* p0 = reinterpret_cast<float2*>(g_lig + (size_t)v0 * EMB + e0);
        float2 o0 = *p0;
        *p0 = make_float2(o0.x + ya0, o0.y + yb0);
        float2* p1 = reinterpret_cast<float2*>(g_lig + (size_t)v1 * EMB + e0);
        float2 o1 = *p1;
        *p1 = make_float2(o1.x + ya1, o1.y + yb1);
    }
}

// ---------------- lazy clean: restore all-zero invariant for next call ----------------
// 64 threads per dirty node; zero its 192 accR floats, reset flag + dlist sentinel.
__global__ void __launch_bounds__(256) k_clean() {
    int dcnt = g_dcnt;
    int stride = (gridDim.x * blockDim.x) >> 6;          // nodes per sweep
    int p0 = (blockIdx.x * blockDim.x + threadIdx.x) >> 6;
    int lane = threadIdx.x & 63;
    for (int p = p0; p < dcnt; p += stride) {
        int n = g_dlist[p];
        float* base = g_accR + (size_t)n * 192;
        base[lane] = 0.f;
        base[64 + lane] = 0.f;
        base[128 + lane] = 0.f;
        if (lane == 0) {
            g_ndirty[n] = 0;
            g_dlist[p] = NODES;   // restore sentinel
        }
    }
}

// ---------------- residue phase: 256 threads, 4 row-pairs x 2 adjacent channels ----------------
#define SMEM_RES_FLOATS (4608 + 4608 + 96 + 96 + 32 + 128 + 32)

__global__ void __launch_bounds__(256, 4) k_res(
    const float* __restrict__ pn, const float* __restrict__ pca, const float* __restrict__ pc,
    const int* __restrict__ rtype, const float* __restrict__ resemb,
    const float* __restrict__ bbW, const float* __restrict__ bbB,
    const float* __restrict__ e1W, const float* __restrict__ e1B,
    const float* __restrict__ e2aW, const float* __restrict__ e2aB,
    const float* __restrict__ e2bW, const float* __restrict__ e2bB,
    const float* __restrict__ sc1W, const float* __restrict__ sc1B,
    const float* __restrict__ sc2W, const float* __restrict__ sc2B,
    float* __restrict__ out)
{
    extern __shared__ float sm[];
    float* bufA = sm;                      // 4608 (rbf then s1)
    float* bufB = sm + 4608;               // 4608 (g, then m-chunks)
    float* sh_p = sm + 9216;               // 96
    float* sh_q = sh_p + 96;               // 96
    float* sh_d = sh_q + 96;               // 32
    float* sh_w14 = sh_d + 32;             // 128 (float4[32]: w0,w1,w2,b)
    float* sh_w2 = sh_w14 + 128;           // 32
    const ulonglong2* bufA2 = reinterpret_cast<const ulonglong2*>(bufA);
    const ulonglong2* bufB2 = reinterpret_cast<const ulonglong2*>(bufB);
    u64* bufAD = reinterpret_cast<u64*>(bufA);
    u64* bufBD = reinterpret_cast<u64*>(bufB);

    int tid = threadIdx.x;
    int n0 = blockIdx.x * TRES;
    int e0 = 2 * (tid & 63), q = tid >> 6, e1 = e0 + 1;
    int rpb = 4 * q;

    if (tid < 32) {
        reinterpret_cast<float4*>(sh_w14)[tid] =
            make_float4(sc1W[tid], sc1W[32 + tid], sc1W[64 + tid], sc1B[tid]);
        sh_w2[tid] = sc2W[tid];
    }
    float b2s = sc2B[0];

    if (tid < TRES) {
        int n = n0 + tid;
        float nx = pn[3 * n], ny = pn[3 * n + 1], nz = pn[3 * n + 2];
        float ax = pca[3 * n], ay = pca[3 * n + 1], az = pca[3 * n + 2];
        float cx = pc[3 * n], cy = pc[3 * n + 1], cz = pc[3 * n + 2];
        float v1x = ax - nx, v1y = ay - ny, v1z = az - nz;
        float d1 = sqrtf(v1x * v1x + v1y * v1y + v1z * v1z);
        float i1 = 1.0f / fmaxf(d1, 1e-8f);
        float f1x = v1x * i1, f1y = v1y * i1, f1z = v1z * i1;
        float v2x = cx - ax, v2y = cy - ay, v2z = cz - az;
        float d2 = sqrtf(v2x * v2x + v2y * v2y + v2z * v2z);
        float i2 = 1.0f / fmaxf(d2, 1e-8f);
        float f2x = v2x * i2, f2y = v2y * i2, f2z = v2z * i2;
        float crx = f1y * f2z - f1z * f2y;
        float cry = f1z * f2x - f1x * f2z;
        float crz = f1x * f2y - f1y * f2x;
        float dc = sqrtf(crx * crx + cry * cry + crz * crz);
        float i3 = 1.0f / fmaxf(dc, 1e-8f);
        float f3x = crx * i3, f3y = cry * i3, f3z = crz * i3;

        int r0 = 2 * tid;
        sh_d[r0] = d1;
        sh_d[r0 + 1] = d2;
        sh_p[r0 * 3 + 0] = v1x * f1x + v1y * f1y + v1z * f1z;
        sh_p[r0 * 3 + 1] = v1x * f2x + v1y * f2y + v1z * f2z;
        sh_p[r0 * 3 + 2] = v1x * f3x + v1y * f3y + v1z * f3z;
        sh_p[(r0 + 1) * 3 + 0] = v2x * f1x + v2y * f1y + v2z * f1z;
        sh_p[(r0 + 1) * 3 + 1] = v2x * f2x + v2y * f2y + v2z * f2z;
        sh_p[(r0 + 1) * 3 + 2] = v2x * f3x + v2y * f3y + v2z * f3z;
        float q0 = f1x + f1y + f1z;
        float q1 = f2x + f2y + f2z;
        float q2 = f3x + f3y + f3z;
        sh_q[r0 * 3 + 0] = q0; sh_q[r0 * 3 + 1] = q1; sh_q[r0 * 3 + 2] = q2;
        sh_q[(r0 + 1) * 3 + 0] = q0; sh_q[(r0 + 1) * 3 + 1] = q1; sh_q[(r0 + 1) * 3 + 2] = q2;
    }
    __syncthreads();

    // ---- rbf, column-major: 4-way row split ----
    {
        int k = tid & 63;
        int rh = tid >> 6;
        float mu = (float)k * (5.0f / 63.0f);
#pragma unroll
        for (int r = rh; r < 32; r += 4) {
            float t = sh_d[r] - mu;
            bufA[k * STRF + r] = __expf(-10.0f * t * t);
        }
    }
    __syncthreads();

    // ---- radial = rbf @ bbW + b ; g = radial*u*v -> bufB ----
    {
        u64 hA[4], hB[4];
        gemm4<64, false>(bufA2, q, bbW, 128, e0, hA, hB);
        float2 bb = *reinterpret_cast<const float2*>(bbB + e0);
#pragma unroll
        for (int jj = 0; jj < 4; jj++) {
            int rp = rpb + jj;
            int n = n0 + rp;
            const float* L = g_lig + (size_t)(3 * n) * EMB;
            float2 u0 = *reinterpret_cast<const float2*>(L + e0);
            float2 u1 = *reinterpret_cast<const float2*>(L + EMB + e0);
            float2 u2 = *reinterpret_cast<const float2*>(L + 2 * EMB + e0);
            float h0, h1;
            up2(hA[jj], h0, h1);
            bufBD[e0 * STRD + rp] = pk2((h0 + bb.x) * u0.x * u1.x, (h1 + bb.x) * u1.x * u2.x);
            up2(hB[jj], h0, h1);
            bufBD[e1 * STRD + rp] = pk2((h0 + bb.y) * u0.y * u1.y, (h1 + bb.y) * u1.y * u2.y);
        }
    }
    __syncthreads();

    // ---- h = g @ e1W ; scalarization + silu-MLP -> s1 in bufA ----
    {
        u64 hA[4], hB[4];
        gemm4<128, false>(bufB2, q, e1W, 128, e0, hA, hB);
        float2 b1c = *reinterpret_cast<const float2*>(e1B + e0);
#pragma unroll 1
        for (int jj = 0; jj < 4; jj++) {
            int rp = rpb + jj;
            int r0 = 2 * rp, r1 = r0 + 1;
            float p00 = sh_p[r0 * 3 + 0], p01 = sh_p[r0 * 3 + 1], p02 = sh_p[r0 * 3 + 2];
            float p10 = sh_p[r1 * 3 + 0], p11 = sh_p[r1 * 3 + 1], p12 = sh_p[r1 * 3 + 2];
            float q0 = sh_q[r0 * 3 + 0], q1 = sh_q[r0 * 3 + 1], q2 = sh_q[r0 * 3 + 2];
            float hA0, hA1, hB0, hB1;
            up2(hA[jj], hA0, hA1);
            up2(hB[jj], hB0, hB1);
            float sA0x = hA0 * p00 + b1c.x * q0, sA0y = hA0 * p01 + b1c.x * q1, sA0z = hA0 * p02 + b1c.x * q2;
            float sA1x = hA1 * p10 + b1c.x * q0, sA1y = hA1 * p11 + b1c.x * q1, sA1z = hA1 * p12 + b1c.x * q2;
            float sB0x = hB0 * p00 + b1c.y * q0, sB0y = hB0 * p01 + b1c.y * q1, sB0z = hB0 * p02 + b1c.y * q2;
            float sB1x = hB1 * p10 + b1c.y * q0, sB1y = hB1 * p11 + b1c.y * q1, sB1z = hB1 * p12 + b1c.y * q2;
            float zA0 = 0.f, zA1 = 0.f, zB0 = 0.f, zB1 = 0.f;
#pragma unroll 1
            for (int m = 0; m < 32; m++) {
                float4 wv = reinterpret_cast<const float4*>(sh_w14)[m];
                float wo = sh_w2[m];
                float t0 = fmaf(sA0x, wv.x, fmaf(sA0y, wv.y, fmaf(sA0z, wv.z, wv.w)));
                float t1 = fmaf(sA1x, wv.x, fmaf(sA1y, wv.y, fmaf(sA1z, wv.z, wv.w)));
                float t2 = fmaf(sB0x, wv.x, fmaf(sB0y, wv.y, fmaf(sB0z, wv.z, wv.w)));
                float t3 = fmaf(sB1x, wv.x, fmaf(sB1y, wv.y, fmaf(sB1z, wv.z, wv.w)));
                zA0 = fmaf(fast_silu(t0), wo, zA0);
                zA1 = fmaf(fast_silu(t1), wo, zA1);
                zB0 = fmaf(fast_silu(t2), wo, zB0);
                zB1 = fmaf(fast_silu(t3), wo, zB1);
            }
            bufAD[e0 * STRD + rp] = pk2(zA0 + b2s + sA0x, zA1 + b2s + sA1x);
            bufAD[e1 * STRD + rp] = pk2(zB0 + b2s + sB0x, zB1 + b2s + sB1x);
        }
    }
    __syncthreads();

    // ---- fused MLP: per 128-ch chunk, m=relu(s1@e2aW)+b in bufB, y += m@e2bW ----
    u64 yA[4], yB[4];
#pragma unroll
    for (int i = 0; i < 4; i++) { yA[i] = 0ull; yB[i] = 0ull; }
#pragma unroll 1
    for (int ch = 0; ch < 2; ch++) {
        u64 mA[4], mB[4];
        gemm4<128, false>(bufA2, q, e2aW + ch * 128, 256, e0, mA, mB);
        float2 ba = *reinterpret_cast<const float2*>(e2aB + ch * 128 + e0);
#pragma unroll
        for (int jj = 0; jj < 4; jj++) {
            int rp = rpb + jj;
            float x0, x1;
            up2(mA[jj], x0, x1);
            bufBD[e0 * STRD + rp] = pk2(fmaxf(x0 + ba.x, 0.f), fmaxf(x1 + ba.x, 0.f));
            up2(mB[jj], x0, x1);
            bufBD[e1 * STRD + rp] = pk2(fmaxf(x0 + ba.y, 0.f), fmaxf(x1 + ba.y, 0.f));
        }
        __syncthreads();
        gemm4<128, true>(bufB2, q, e2bW + ch * 128 * 128, 128, e0, yA, yB);
        __syncthreads();
    }

    // ---- epilogue (float2 stores) ----
    {
        float2 bb2 = *reinterpret_cast<const float2*>(e2bB + e0);
#pragma unroll
        for (int jj = 0; jj < 4; jj++) {
            int rp = rpb + jj;
            int n = n0 + rp;
            int rt = rtype[n];
            float2 re = *reinterpret_cast<const float2*>(resemb + (size_t)rt * EMB + e0);
            float ya0, ya1, yb0, yb1;
            up2(yA[jj], ya0, ya1);
            up2(yB[jj], yb0, yb1);
            float2 r;
            r.x = 0.5f * (ya0 + ya1) + bb2.x + re.x;
            r.y = 0.5f * (yb0 + yb1) + bb2.y + re.y;
            *reinterpret_cast<float2*>(out + (size_t)n * EMB + e0) = r;
        }
    }
}

// ---------------- launch ----------------
extern "C" void kernel_launch(void* const* d_in, const int* in_sizes, int n_in,
                              void* d_out, int out_size) {
    const float* pn    = (const float*)d_in[0];
    const float* pca   = (const float*)d_in[1];
    const float* pc    = (const float*)d_in[2];
    const int*   rtype = (const int*)  d_in[3];
    /* batch d_in[4] unused */
    const int*   eidx  = (const int*)  d_in[5];
    const float* resemb= (const float*)d_in[6];
    const float* bbemb = (const float*)d_in[7];
    const float* ligW  = (const float*)d_in[8];
    const float* ligb  = (const float*)d_in[9];
    const float* bbW   = (const float*)d_in[10];
    const float* bbB   = (const float*)d_in[11];
    const float* e1W   = (const float*)d_in[12];
    const float* e1B   = (const float*)d_in[13];
    const float* e2aW  = (const float*)d_in[14];
    const float* e2aB  = (const float*)d_in[15];
    const float* e2bW  = (const float*)d_in[16];
    const float* e2bB  = (const float*)d_in[17];
    const float* sc1W  = (const float*)d_in[18];
    const float* sc1B  = (const float*)d_in[19];
    const float* sc2W  = (const float*)d_in[20];
    const float* sc2B  = (const float*)d_in[21];
    float* out = (float*)d_out;

    size_t smem_res = SMEM_RES_FLOATS * sizeof(float);
    cudaFuncSetAttribute(k_res, cudaFuncAttributeMaxDynamicSharedMemorySize, (int)smem_res);
    cudaFuncSetAttribute(k_res, cudaFuncAttributePreferredSharedMemoryCarveout, 100);
    cudaFuncSetAttribute(k_lig_fix, cudaFuncAttributePreferredSharedMemoryCarveout, 100);

    k_init<<<256, 256>>>(pn, pca, pc, ligW, ligb, bbemb);
    k_edge<<<NEDGE / 256, 256>>>(eidx);
    k_lig_all<<<NODES / 4, 256>>>(bbemb);
    k_lig_fix<<<NODES / 32, 256>>>();
    k_res<<<NRES / TRES, 256, smem_res>>>(pn, pca, pc, rtype, resemb,
                                          bbW, bbB, e1W, e1B,
                                          e2aW, e2aB, e2bW, e2bB,
                                          sc1W, sc1B, sc2W, sc2B, out);
    k_clean<<<1024, 256>>>();
}

// round 13
// speedup vs baseline: 1.1121x; 1.1121x over previous
#include <cuda_runtime.h>
#include <math.h>

#define NRES  16384
#define NODES 49152
#define NODESP (NODES + 32)
#define NEDGE 786432
#define EMB   128
#define NRAD  64
#define TRES  16
#define STRF  36   // activation column stride in floats
#define STRD  18   // in u64
#define STRV  9    // in ulonglong2

typedef unsigned long long u64;

__device__ __forceinline__ u64 pk2(float lo, float hi) {
    u64 r; asm("mov.b64 %0,{%1,%2};" : "=l"(r) : "f"(lo), "f"(hi)); return r;
}
__device__ __forceinline__ u64 pkw(float w) {
    u64 r; asm("mov.b64 %0,{%1,%1};" : "=l"(r) : "f"(w)); return r;
}
__device__ __forceinline__ void up2(u64 a, float& lo, float& hi) {
    asm("mov.b64 {%0,%1},%2;" : "=f"(lo), "=f"(hi) : "l"(a));
}
__device__ __forceinline__ u64 ff2(u64 a, u64 b, u64 c) {
    u64 d; asm("fma.rn.f32x2 %0,%1,%2,%3;" : "=l"(d) : "l"(a), "l"(b), "l"(c)); return d;
}
__device__ __forceinline__ float fast_silu(float t) {
    float h = 0.5f * t, th;
    asm("tanh.approx.f32 %0,%1;" : "=f"(th) : "f"(h));
    return fmaf(h, th, h);
}

// ---------------- device scratch ----------------
__device__ float4 g_pos[NODES];
__device__ float  g_cnt[NODESP * 3];
__device__ float  g_lig[(size_t)NODESP * EMB];
__device__ float  g_bp[3 * EMB];
__device__ float  g_Wp[192 * EMB];     // Wp[t*64+k][c] = ligW[k][c]*bbemb[t][c]
__device__ int2   g_elist[NEDGE];      // in-cutoff edge records {(i<<2)|tj, bits(d)}
__device__ int    g_ecnt;

// ---------------- init ----------------
__global__ void __launch_bounds__(256) k_init(const float* __restrict__ pn,
                                              const float* __restrict__ pca,
                                              const float* __restrict__ pc,
                                              const float* __restrict__ ligW,
                                              const float* __restrict__ ligb,
                                              const float* __restrict__ bbemb) {
    int idx = blockIdx.x * blockDim.x + threadIdx.x;
    int stride = gridDim.x * blockDim.x;
    const int n2 = (NODESP * 3) / 4;
    float4 z = make_float4(0.f, 0.f, 0.f, 0.f);
    float4* cvec = reinterpret_cast<float4*>(g_cnt);
    for (int i = idx; i < n2; i += stride) cvec[i] = z;
    if (idx == 0) g_ecnt = 0;

    if (idx < NRES) {
        int n = idx;
        g_pos[3 * n + 0] = make_float4(pn[3 * n], pn[3 * n + 1], pn[3 * n + 2], 0.f);
        g_pos[3 * n + 1] = make_float4(pca[3 * n], pca[3 * n + 1], pca[3 * n + 2], 0.f);
        g_pos[3 * n + 2] = make_float4(pc[3 * n], pc[3 * n + 1], pc[3 * n + 2], 0.f);
    }
    if (idx < 192 * EMB) {
        int c = idx & 127;
        int kk = idx >> 7;
        int t = kk / NRAD;
        int k = kk - t * NRAD;
        g_Wp[idx] = ligW[k * EMB + c] * bbemb[t * EMB + c];
    }
    if (idx < 3 * EMB) g_bp[idx] = ligb[idx & 127] * bbemb[idx];
}

// ---------------- edge phase: count + compact in-cutoff records ----------------
__global__ void __launch_bounds__(256) k_edge(const int* __restrict__ ei) {
    int e = blockIdx.x * blockDim.x + threadIdx.x;
    if (e >= NEDGE) return;
    int i = ei[e];
    int j = ei[NEDGE + e];
    float4 pi = g_pos[i];
    float4 pj = g_pos[j];
    float dx = pi.x - pj.x, dy = pi.y - pj.y, dz = pi.z - pj.z;
    float d2 = dx * dx + dy * dy + dz * dz;
    int tj = j % 3;
    atomicAdd(&g_cnt[i * 3 + tj], 1.0f);
    if (d2 < 44.0f) {
        int p = atomicAdd(&g_ecnt, 1);
        g_elist[p] = make_int2((i << 2) | tj, __float_as_int(sqrtf(d2)));
    }
}

// ---------------- closed-form lig for ALL nodes ----------------
__global__ void __launch_bounds__(256) k_lig_all(const float* __restrict__ bbemb) {
    int idx = blockIdx.x * blockDim.x + threadIdx.x;
    int n = idx >> 6;
    int e0 = 2 * (idx & 63);
    if (n >= NODES) return;
    float c0 = g_cnt[n * 3 + 0], c1 = g_cnt[n * 3 + 1], c2 = g_cnt[n * 3 + 2];
    float deg = c0 + c1 + c2;
    int a = n % 3;
    float2 xs = *reinterpret_cast<const float2*>(bbemb + a * EMB + e0);
    float2 b0 = *reinterpret_cast<const float2*>(g_bp + e0);
    float2 b1 = *reinterpret_cast<const float2*>(g_bp + EMB + e0);
    float2 b2 = *reinterpret_cast<const float2*>(g_bp + 2 * EMB + e0);
    float2 r;
    r.x = deg * xs.x + c0 * b0.x + c1 * b1.x + c2 * b2.x;
    r.y = deg * xs.y + c0 * b0.y + c1 * b1.y + c2 * b2.y;
    *reinterpret_cast<float2*>(g_lig + (size_t)n * EMB + e0) = r;
}

// ---------------- per-edge correction: lig[i] += rbf(d) @ Wp[tj] ----------------
// One warp per edge. Lanes: rbf in smem (2 bins each), then 4 channels each.
__global__ void __launch_bounds__(256) k_fix() {
    __shared__ float srbf[8][64];
    int wid = threadIdx.x >> 5, lane = threadIdx.x & 31;
    int nwarp = gridDim.x * 8;
    int ecnt = g_ecnt;
    const float step = 5.0f / 63.0f;
    for (int e = blockIdx.x * 8 + wid; e < ecnt; e += nwarp) {
        int2 rec = g_elist[e];
        int i = rec.x >> 2, tj = rec.x & 3;
        float d = __int_as_float(rec.y);
        float t0 = d - (2 * lane) * step;
        float t1 = d - (2 * lane + 1) * step;
        srbf[wid][2 * lane] = __expf(-10.0f * t0 * t0);
        srbf[wid][2 * lane + 1] = __expf(-10.0f * t1 * t1);
        __syncwarp();
        const ulonglong2* W = reinterpret_cast<const ulonglong2*>(g_Wp + tj * 64 * EMB + 4 * lane);
        u64 a0 = 0ull, a1 = 0ull;
#pragma unroll 4
        for (int k = 0; k < 64; k++) {
            float r = srbf[wid][k];
            u64 rp = pkw(r);
            ulonglong2 wv = __ldg(W + k * 32);   // stride 128 floats = 32 ulonglong2
            a0 = ff2(rp, wv.x, a0);
            a1 = ff2(rp, wv.y, a1);
        }
        float v0, v1, v2, v3;
        up2(a0, v0, v1);
        up2(a1, v2, v3);
        unsigned long long gaddr = (unsigned long long)
            __cvta_generic_to_global(g_lig + (size_t)i * EMB + 4 * lane);
        asm volatile("red.global.add.v4.f32 [%0], {%1,%2,%3,%4};"
                     :: "l"(gaddr), "f"(v0), "f"(v1), "f"(v2), "f"(v3) : "memory");
        __syncwarp();
    }
}

// ---------------- FMA2 GEMM: 4 row-pairs, adjacent channel pair (e0, e0+1) ----------------
template<int K, bool ACC>
__device__ __forceinline__ void gemm4(const ulonglong2* __restrict__ X, int q,
                                      const float* __restrict__ W, int ldw,
                                      int e0, u64* aA, u64* aB) {
    if (!ACC) {
#pragma unroll
        for (int i = 0; i < 4; i++) { aA[i] = 0ull; aB[i] = 0ull; }
    }
    const ulonglong2* xp = X + 2 * q;
#pragma unroll 4
    for (int k = 0; k < K; k++) {
        float2 wv = __ldg(reinterpret_cast<const float2*>(W + (size_t)k * ldw + e0));
        u64 w0 = pkw(wv.x);
        u64 w1 = pkw(wv.y);
        ulonglong2 x0 = xp[k * STRV + 0];
        ulonglong2 x1 = xp[k * STRV + 1];
        aA[0] = ff2(x0.x, w0, aA[0]); aA[1] = ff2(x0.y, w0, aA[1]);
        aA[2] = ff2(x1.x, w0, aA[2]); aA[3] = ff2(x1.y, w0, aA[3]);
        aB[0] = ff2(x0.x, w1, aB[0]); aB[1] = ff2(x0.y, w1, aB[1]);
        aB[2] = ff2(x1.x, w1, aB[2]); aB[3] = ff2(x1.y, w1, aB[3]);
    }
}

// ---------------- residue phase (unchanged from R9/R11 best) ----------------
#define SMEM_RES_FLOATS (4608 + 4608 + 96 + 96 + 32 + 128 + 32)

__global__ void __launch_bounds__(256, 4) k_res(
    const float* __restrict__ pn, const float* __restrict__ pca, const float* __restrict__ pc,
    const int* __restrict__ rtype, const float* __restrict__ resemb,
    const float* __restrict__ bbW, const float* __restrict__ bbB,
    const float* __restrict__ e1W, const float* __restrict__ e1B,
    const float* __restrict__ e2aW, const float* __restrict__ e2aB,
    const float* __restrict__ e2bW, const float* __restrict__ e2bB,
    const float* __restrict__ sc1W, const float* __restrict__ sc1B,
    const float* __restrict__ sc2W, const float* __restrict__ sc2B,
    float* __restrict__ out)
{
    extern __shared__ float sm[];
    float* bufA = sm;                      // 4608 (rbf then s1)
    float* bufB = sm + 4608;               // 4608 (g, then m-chunks)
    float* sh_p = sm + 9216;               // 96
    float* sh_q = sh_p + 96;               // 96
    float* sh_d = sh_q + 96;               // 32
    float* sh_w14 = sh_d + 32;             // 128 (float4[32]: w0,w1,w2,b)
    float* sh_w2 = sh_w14 + 128;           // 32
    const ulonglong2* bufA2 = reinterpret_cast<const ulonglong2*>(bufA);
    const ulonglong2* bufB2 = reinterpret_cast<const ulonglong2*>(bufB);
    u64* bufAD = reinterpret_cast<u64*>(bufA);
    u64* bufBD = reinterpret_cast<u64*>(bufB);

    int tid = threadIdx.x;
    int n0 = blockIdx.x * TRES;
    int e0 = 2 * (tid & 63), q = tid >> 6, e1 = e0 + 1;
    int rpb = 4 * q;

    if (tid < 32) {
        reinterpret_cast<float4*>(sh_w14)[tid] =
            make_float4(sc1W[tid], sc1W[32 + tid], sc1W[64 + tid], sc1B[tid]);
        sh_w2[tid] = sc2W[tid];
    }
    float b2s = sc2B[0];

    if (tid < TRES) {
        int n = n0 + tid;
        float nx = pn[3 * n], ny = pn[3 * n + 1], nz = pn[3 * n + 2];
        float ax = pca[3 * n], ay = pca[3 * n + 1], az = pca[3 * n + 2];
        float cx = pc[3 * n], cy = pc[3 * n + 1], cz = pc[3 * n + 2];
        float v1x = ax - nx, v1y = ay - ny, v1z = az - nz;
        float d1 = sqrtf(v1x * v1x + v1y * v1y + v1z * v1z);
        float i1 = 1.0f / fmaxf(d1, 1e-8f);
        float f1x = v1x * i1, f1y = v1y * i1, f1z = v1z * i1;
        float v2x = cx - ax, v2y = cy - ay, v2z = cz - az;
        float d2 = sqrtf(v2x * v2x + v2y * v2y + v2z * v2z);
        float i2 = 1.0f / fmaxf(d2, 1e-8f);
        float f2x = v2x * i2, f2y = v2y * i2, f2z = v2z * i2;
        float crx = f1y * f2z - f1z * f2y;
        float cry = f1z * f2x - f1x * f2z;
        float crz = f1x * f2y - f1y * f2x;
        float dc = sqrtf(crx * crx + cry * cry + crz * crz);
        float i3 = 1.0f / fmaxf(dc, 1e-8f);
        float f3x = crx * i3, f3y = cry * i3, f3z = crz * i3;

        int r0 = 2 * tid;
        sh_d[r0] = d1;
        sh_d[r0 + 1] = d2;
        sh_p[r0 * 3 + 0] = v1x * f1x + v1y * f1y + v1z * f1z;
        sh_p[r0 * 3 + 1] = v1x * f2x + v1y * f2y + v1z * f2z;
        sh_p[r0 * 3 + 2] = v1x * f3x + v1y * f3y + v1z * f3z;
        sh_p[(r0 + 1) * 3 + 0] = v2x * f1x + v2y * f1y + v2z * f1z;
        sh_p[(r0 + 1) * 3 + 1] = v2x * f2x + v2y * f2y + v2z * f2z;
        sh_p[(r0 + 1) * 3 + 2] = v2x * f3x + v2y * f3y + v2z * f3z;
        float q0 = f1x + f1y + f1z;
        float q1 = f2x + f2y + f2z;
        float q2 = f3x + f3y + f3z;
        sh_q[r0 * 3 + 0] = q0; sh_q[r0 * 3 + 1] = q1; sh_q[r0 * 3 + 2] = q2;
        sh_q[(r0 + 1) * 3 + 0] = q0; sh_q[(r0 + 1) * 3 + 1] = q1; sh_q[(r0 + 1) * 3 + 2] = q2;
    }
    __syncthreads();

    // ---- rbf, column-major: 4-way row split ----
    {
        int k = tid & 63;
        int rh = tid >> 6;
        float mu = (float)k * (5.0f / 63.0f);
#pragma unroll
        for (int r = rh; r < 32; r += 4) {
            float t = sh_d[r] - mu;
            bufA[k * STRF + r] = __expf(-10.0f * t * t);
        }
    }
    __syncthreads();

    // ---- radial = rbf @ bbW + b ; g = radial*u*v -> bufB ----
    {
        u64 hA[4], hB[4];
        gemm4<64, false>(bufA2, q, bbW, 128, e0, hA, hB);
        float2 bb = *reinterpret_cast<const float2*>(bbB + e0);
#pragma unroll
        for (int jj = 0; jj < 4; jj++) {
            int rp = rpb + jj;
            int n = n0 + rp;
            const float* L = g_lig + (size_t)(3 * n) * EMB;
            float2 u0 = *reinterpret_cast<const float2*>(L + e0);
            float2 u1 = *reinterpret_cast<const float2*>(L + EMB + e0);
            float2 u2 = *reinterpret_cast<const float2*>(L + 2 * EMB + e0);
            float h0, h1;
            up2(hA[jj], h0, h1);
            bufBD[e0 * STRD + rp] = pk2((h0 + bb.x) * u0.x * u1.x, (h1 + bb.x) * u1.x * u2.x);
            up2(hB[jj], h0, h1);
            bufBD[e1 * STRD + rp] = pk2((h0 + bb.y) * u0.y * u1.y, (h1 + bb.y) * u1.y * u2.y);
        }
    }
    __syncthreads();

    // ---- h = g @ e1W ; scalarization + silu-MLP -> s1 in bufA ----
    {
        u64 hA[4], hB[4];
        gemm4<128, false>(bufB2, q, e1W, 128, e0, hA, hB);
        float2 b1c = *reinterpret_cast<const float2*>(e1B + e0);
#pragma unroll 1
        for (int jj = 0; jj < 4; jj++) {
            int rp = rpb + jj;
            int r0 = 2 * rp, r1 = r0 + 1;
            float p00 = sh_p[r0 * 3 + 0], p01 = sh_p[r0 * 3 + 1], p02 = sh_p[r0 * 3 + 2];
            float p10 = sh_p[r1 * 3 + 0], p11 = sh_p[r1 * 3 + 1], p12 = sh_p[r1 * 3 + 2];
            float q0 = sh_q[r0 * 3 + 0], q1 = sh_q[r0 * 3 + 1], q2 = sh_q[r0 * 3 + 2];
            float hA0, hA1, hB0, hB1;
            up2(hA[jj], hA0, hA1);
            up2(hB[jj], hB0, hB1);
            float sA0x = hA0 * p00 + b1c.x * q0, sA0y = hA0 * p01 + b1c.x * q1, sA0z = hA0 * p02 + b1c.x * q2;
            float sA1x = hA1 * p10 + b1c.x * q0, sA1y = hA1 * p11 + b1c.x * q1, sA1z = hA1 * p12 + b1c.x * q2;
            float sB0x = hB0 * p00 + b1c.y * q0, sB0y = hB0 * p01 + b1c.y * q1, sB0z = hB0 * p02 + b1c.y * q2;
            float sB1x = hB1 * p10 + b1c.y * q0, sB1y = hB1 * p11 + b1c.y * q1, sB1z = hB1 * p12 + b1c.y * q2;
            float zA0 = 0.f, zA1 = 0.f, zB0 = 0.f, zB1 = 0.f;
#pragma unroll 1
            for (int m = 0; m < 32; m++) {
                float4 wv = reinterpret_cast<const float4*>(sh_w14)[m];
                float wo = sh_w2[m];
                float t0 = fmaf(sA0x, wv.x, fmaf(sA0y, wv.y, fmaf(sA0z, wv.z, wv.w)));
                float t1 = fmaf(sA1x, wv.x, fmaf(sA1y, wv.y, fmaf(sA1z, wv.z, wv.w)));
                float t2 = fmaf(sB0x, wv.x, fmaf(sB0y, wv.y, fmaf(sB0z, wv.z, wv.w)));
                float t3 = fmaf(sB1x, wv.x, fmaf(sB1y, wv.y, fmaf(sB1z, wv.z, wv.w)));
                zA0 = fmaf(fast_silu(t0), wo, zA0);
                zA1 = fmaf(fast_silu(t1), wo, zA1);
                zB0 = fmaf(fast_silu(t2), wo, zB0);
                zB1 = fmaf(fast_silu(t3), wo, zB1);
            }
            bufAD[e0 * STRD + rp] = pk2(zA0 + b2s + sA0x, zA1 + b2s + sA1x);
            bufAD[e1 * STRD + rp] = pk2(zB0 + b2s + sB0x, zB1 + b2s + sB1x);
        }
    }
    __syncthreads();

    // ---- fused MLP: per 128-ch chunk, m=relu(s1@e2aW)+b in bufB, y += m@e2bW ----
    u64 yA[4], yB[4];
#pragma unroll
    for (int i = 0; i < 4; i++) { yA[i] = 0ull; yB[i] = 0ull; }
#pragma unroll 1
    for (int ch = 0; ch < 2; ch++) {
        u64 mA[4], mB[4];
        gemm4<128, false>(bufA2, q, e2aW + ch * 128, 256, e0, mA, mB);
        float2 ba = *reinterpret_cast<const float2*>(e2aB + ch * 128 + e0);
#pragma unroll
        for (int jj = 0; jj < 4; jj++) {
            int rp = rpb + jj;
            float x0, x1;
            up2(mA[jj], x0, x1);
            bufBD[e0 * STRD + rp] = pk2(fmaxf(x0 + ba.x, 0.f), fmaxf(x1 + ba.x, 0.f));
            up2(mB[jj], x0, x1);
            bufBD[e1 * STRD + rp] = pk2(fmaxf(x0 + ba.y, 0.f), fmaxf(x1 + ba.y, 0.f));
        }
        __syncthreads();
        gemm4<128, true>(bufB2, q, e2bW + ch * 128 * 128, 128, e0, yA, yB);
        __syncthreads();
    }

    // ---- epilogue (float2 stores) ----
    {
        float2 bb2 = *reinterpret_cast<const float2*>(e2bB + e0);
#pragma unroll
        for (int jj = 0; jj < 4; jj++) {
            int rp = rpb + jj;
            int n = n0 + rp;
            int rt = rtype[n];
            float2 re = *reinterpret_cast<const float2*>(resemb + (size_t)rt * EMB + e0);
            float ya0, ya1, yb0, yb1;
            up2(yA[jj], ya0, ya1);
            up2(yB[jj], yb0, yb1);
            float2 r;
            r.x = 0.5f * (ya0 + ya1) + bb2.x + re.x;
            r.y = 0.5f * (yb0 + yb1) + bb2.y + re.y;
            *reinterpret_cast<float2*>(out + (size_t)n * EMB + e0) = r;
        }
    }
}

// ---------------- launch ----------------
extern "C" void kernel_launch(void* const* d_in, const int* in_sizes, int n_in,
                              void* d_out, int out_size) {
    const float* pn    = (const float*)d_in[0];
    const float* pca   = (const float*)d_in[1];
    const float* pc    = (const float*)d_in[2];
    const int*   rtype = (const int*)  d_in[3];
    /* batch d_in[4] unused */
    const int*   eidx  = (const int*)  d_in[5];
    const float* resemb= (const float*)d_in[6];
    const float* bbemb = (const float*)d_in[7];
    const float* ligW  = (const float*)d_in[8];
    const float* ligb  = (const float*)d_in[9];
    const float* bbW   = (const float*)d_in[10];
    const float* bbB   = (const float*)d_in[11];
    const float* e1W   = (const float*)d_in[12];
    const float* e1B   = (const float*)d_in[13];
    const float* e2aW  = (const float*)d_in[14];
    const float* e2aB  = (const float*)d_in[15];
    const float* e2bW  = (const float*)d_in[16];
    const float* e2bB  = (const float*)d_in[17];
    const float* sc1W  = (const float*)d_in[18];
    const float* sc1B  = (const float*)d_in[19];
    const float* sc2W  = (const float*)d_in[20];
    const float* sc2B  = (const float*)d_in[21];
    float* out = (float*)d_out;

    size_t smem_res = SMEM_RES_FLOATS * sizeof(float);
    cudaFuncSetAttribute(k_res, cudaFuncAttributeMaxDynamicSharedMemorySize, (int)smem_res);
    cudaFuncSetAttribute(k_res, cudaFuncAttributePreferredSharedMemoryCarveout, 100);

    k_init<<<256, 256>>>(pn, pca, pc, ligW, ligb, bbemb);
    k_edge<<<NEDGE / 256, 256>>>(eidx);
    k_lig_all<<<NODES / 4, 256>>>(bbemb);
    k_fix<<<592, 256>>>();
    k_res<<<NRES / TRES, 256, smem_res>>>(pn, pca, pc, rtype, resemb,
                                          bbW, bbB, e1W, e1B,
                                          e2aW, e2aB, e2bW, e2bB,
                                          sc1W, sc1B, sc2W, sc2B, out);
}

// round 15
// speedup vs baseline: 1.1899x; 1.0699x over previous
#include <cuda_runtime.h>
#include <math.h>

#define NRES  16384
#define NODES 49152
#define NODESP (NODES + 32)
#define NEDGE 786432
#define EMB   128
#define NRAD  64
#define TRES  16
#define STRF  36   // activation column stride in floats
#define STRD  18   // in u64
#define STRV  9    // in ulonglong2

typedef unsigned long long u64;

__device__ __forceinline__ u64 pk2(float lo, float hi) {
    u64 r; asm("mov.b64 %0,{%1,%2};" : "=l"(r) : "f"(lo), "f"(hi)); return r;
}
__device__ __forceinline__ u64 pkw(float w) {
    u64 r; asm("mov.b64 %0,{%1,%1};" : "=l"(r) : "f"(w)); return r;
}
__device__ __forceinline__ void up2(u64 a, float& lo, float& hi) {
    asm("mov.b64 {%0,%1},%2;" : "=f"(lo), "=f"(hi) : "l"(a));
}
__device__ __forceinline__ u64 ff2(u64 a, u64 b, u64 c) {
    u64 d; asm("fma.rn.f32x2 %0,%1,%2,%3;" : "=l"(d) : "l"(a), "l"(b), "l"(c)); return d;
}
__device__ __forceinline__ float fast_silu(float t) {
    float h = 0.5f * t, th;
    asm("tanh.approx.f32 %0,%1;" : "=f"(th) : "f"(h));
    return fmaf(h, th, h);
}

// ---------------- device scratch ----------------
__device__ float4 g_pos[NODES];
__device__ float  g_cnt[NODESP * 3];
__device__ float  g_lig[(size_t)NODESP * EMB];
__device__ float  g_bp[3 * EMB];
__device__ float  g_Wp[192 * EMB];     // Wp[t*64+k][c] = ligW[k][c]*bbemb[t][c]
__device__ int2   g_elist[NEDGE];      // in-cutoff edge records {(i<<2)|tj, bits(d)}
__device__ int    g_ecnt;

// ---------------- init ----------------
__global__ void __launch_bounds__(256) k_init(const float* __restrict__ pn,
                                              const float* __restrict__ pca,
                                              const float* __restrict__ pc,
                                              const float* __restrict__ ligW,
                                              const float* __restrict__ ligb,
                                              const float* __restrict__ bbemb) {
    int idx = blockIdx.x * blockDim.x + threadIdx.x;
    int stride = gridDim.x * blockDim.x;
    const int n2 = (NODESP * 3) / 4;
    float4 z = make_float4(0.f, 0.f, 0.f, 0.f);
    float4* cvec = reinterpret_cast<float4*>(g_cnt);
    for (int i = idx; i < n2; i += stride) cvec[i] = z;
    if (idx == 0) g_ecnt = 0;

    if (idx < NRES) {
        int n = idx;
        g_pos[3 * n + 0] = make_float4(pn[3 * n], pn[3 * n + 1], pn[3 * n + 2], 0.f);
        g_pos[3 * n + 1] = make_float4(pca[3 * n], pca[3 * n + 1], pca[3 * n + 2], 0.f);
        g_pos[3 * n + 2] = make_float4(pc[3 * n], pc[3 * n + 1], pc[3 * n + 2], 0.f);
    }
    if (idx < 192 * EMB) {
        int c = idx & 127;
        int kk = idx >> 7;
        int t = kk / NRAD;
        int k = kk - t * NRAD;
        g_Wp[idx] = ligW[k * EMB + c] * bbemb[t * EMB + c];
    }
    if (idx < 3 * EMB) g_bp[idx] = ligb[idx & 127] * bbemb[idx];
}

// ---------------- edge phase: count + compact in-cutoff records ----------------
// record only if some rbf bin has |d-mu| <= 1.35 (mu in [0,5]) -> d < 6.35, d2 < 40.32
__global__ void __launch_bounds__(256) k_edge(const int* __restrict__ ei) {
    int e = blockIdx.x * blockDim.x + threadIdx.x;
    if (e >= NEDGE) return;
    int i = ei[e];
    int j = ei[NEDGE + e];
    float4 pi = g_pos[i];
    float4 pj = g_pos[j];
    float dx = pi.x - pj.x, dy = pi.y - pj.y, dz = pi.z - pj.z;
    float d2 = dx * dx + dy * dy + dz * dz;
    int tj = j % 3;
    atomicAdd(&g_cnt[i * 3 + tj], 1.0f);
    if (d2 < 40.32f) {
        int p = atomicAdd(&g_ecnt, 1);
        g_elist[p] = make_int2((i << 2) | tj, __float_as_int(sqrtf(d2)));
    }
}

// ---------------- closed-form lig for ALL nodes ----------------
__global__ void __launch_bounds__(256) k_lig_all(const float* __restrict__ bbemb) {
    int idx = blockIdx.x * blockDim.x + threadIdx.x;
    int n = idx >> 6;
    int e0 = 2 * (idx & 63);
    if (n >= NODES) return;
    float c0 = g_cnt[n * 3 + 0], c1 = g_cnt[n * 3 + 1], c2 = g_cnt[n * 3 + 2];
    float deg = c0 + c1 + c2;
    int a = n % 3;
    float2 xs = *reinterpret_cast<const float2*>(bbemb + a * EMB + e0);
    float2 b0 = *reinterpret_cast<const float2*>(g_bp + e0);
    float2 b1 = *reinterpret_cast<const float2*>(g_bp + EMB + e0);
    float2 b2 = *reinterpret_cast<const float2*>(g_bp + 2 * EMB + e0);
    float2 r;
    r.x = deg * xs.x + c0 * b0.x + c1 * b1.x + c2 * b2.x;
    r.y = deg * xs.y + c0 * b0.y + c1 * b1.y + c2 * b2.y;
    *reinterpret_cast<float2*>(g_lig + (size_t)n * EMB + e0) = r;
}

// ---------------- per-edge correction: lig[i] += rbf(d) @ Wp[tj], truncated support ----------------
__global__ void __launch_bounds__(256) k_fix() {
    __shared__ float srbf[8][64];
    int wid = threadIdx.x >> 5, lane = threadIdx.x & 31;
    int nwarp = gridDim.x * 8;
    int ecnt = g_ecnt;
    const float step = 5.0f / 63.0f;
    const float inv_step = 63.0f / 5.0f;
    for (int e = blockIdx.x * 8 + wid; e < ecnt; e += nwarp) {
        int2 rec = g_elist[e];
        int i = rec.x >> 2, tj = rec.x & 3;
        float d = __int_as_float(rec.y);
        float t0 = d - (2 * lane) * step;
        float t1 = d - (2 * lane + 1) * step;
        srbf[wid][2 * lane] = __expf(-10.0f * t0 * t0);
        srbf[wid][2 * lane + 1] = __expf(-10.0f * t1 * t1);
        __syncwarp();
        // support: |d - mu_k| <= 1.35 -> dropped terms < 1.2e-8
        int klo = max(0, (int)ceilf((d - 1.35f) * inv_step));
        int khi = min(63, (int)floorf((d + 1.35f) * inv_step));
        const ulonglong2* W = reinterpret_cast<const ulonglong2*>(g_Wp + tj * 64 * EMB + 4 * lane);
        u64 a0 = 0ull, a1 = 0ull;
#pragma unroll 2
        for (int k = klo; k <= khi; k++) {
            float r = srbf[wid][k];
            u64 rp = pkw(r);
            ulonglong2 wv = __ldg(W + k * 32);   // stride 128 floats = 32 ulonglong2
            a0 = ff2(rp, wv.x, a0);
            a1 = ff2(rp, wv.y, a1);
        }
        float v0, v1, v2, v3;
        up2(a0, v0, v1);
        up2(a1, v2, v3);
        unsigned long long gaddr = (unsigned long long)
            __cvta_generic_to_global(g_lig + (size_t)i * EMB + 4 * lane);
        asm volatile("red.global.add.v4.f32 [%0], {%1,%2,%3,%4};"
                     :: "l"(gaddr), "f"(v0), "f"(v1), "f"(v2), "f"(v3) : "memory");
        __syncwarp();
    }
}

// ---------------- FMA2 GEMM: 4 row-pairs, adjacent channel pair (e0, e0+1) ----------------
template<int K, bool ACC>
__device__ __forceinline__ void gemm4(const ulonglong2* __restrict__ X, int q,
                                      const float* __restrict__ W, int ldw,
                                      int e0, u64* aA, u64* aB) {
    if (!ACC) {
#pragma unroll
        for (int i = 0; i < 4; i++) { aA[i] = 0ull; aB[i] = 0ull; }
    }
    const ulonglong2* xp = X + 2 * q;
#pragma unroll 4
    for (int k = 0; k < K; k++) {
        float2 wv = __ldg(reinterpret_cast<const float2*>(W + (size_t)k * ldw + e0));
        u64 w0 = pkw(wv.x);
        u64 w1 = pkw(wv.y);
        ulonglong2 x0 = xp[k * STRV + 0];
        ulonglong2 x1 = xp[k * STRV + 1];
        aA[0] = ff2(x0.x, w0, aA[0]); aA[1] = ff2(x0.y, w0, aA[1]);
        aA[2] = ff2(x1.x, w0, aA[2]); aA[3] = ff2(x1.y, w0, aA[3]);
        aB[0] = ff2(x0.x, w1, aB[0]); aB[1] = ff2(x0.y, w1, aB[1]);
        aB[2] = ff2(x1.x, w1, aB[2]); aB[3] = ff2(x1.y, w1, aB[3]);
    }
}

// ---------------- residue phase (unchanged) ----------------
#define SMEM_RES_FLOATS (4608 + 4608 + 96 + 96 + 32 + 128 + 32)

__global__ void __launch_bounds__(256, 4) k_res(
    const float* __restrict__ pn, const float* __restrict__ pca, const float* __restrict__ pc,
    const int* __restrict__ rtype, const float* __restrict__ resemb,
    const float* __restrict__ bbW, const float* __restrict__ bbB,
    const float* __restrict__ e1W, const float* __restrict__ e1B,
    const float* __restrict__ e2aW, const float* __restrict__ e2aB,
    const float* __restrict__ e2bW, const float* __restrict__ e2bB,
    const float* __restrict__ sc1W, const float* __restrict__ sc1B,
    const float* __restrict__ sc2W, const float* __restrict__ sc2B,
    float* __restrict__ out)
{
    extern __shared__ float sm[];
    float* bufA = sm;                      // 4608 (rbf then s1)
    float* bufB = sm + 4608;               // 4608 (g, then m-chunks)
    float* sh_p = sm + 9216;               // 96
    float* sh_q = sh_p + 96;               // 96
    float* sh_d = sh_q + 96;               // 32
    float* sh_w14 = sh_d + 32;             // 128 (float4[32]: w0,w1,w2,b)
    float* sh_w2 = sh_w14 + 128;           // 32
    const ulonglong2* bufA2 = reinterpret_cast<const ulonglong2*>(bufA);
    const ulonglong2* bufB2 = reinterpret_cast<const ulonglong2*>(bufB);
    u64* bufAD = reinterpret_cast<u64*>(bufA);
    u64* bufBD = reinterpret_cast<u64*>(bufB);

    int tid = threadIdx.x;
    int n0 = blockIdx.x * TRES;
    int e0 = 2 * (tid & 63), q = tid >> 6, e1 = e0 + 1;
    int rpb = 4 * q;

    if (tid < 32) {
        reinterpret_cast<float4*>(sh_w14)[tid] =
            make_float4(sc1W[tid], sc1W[32 + tid], sc1W[64 + tid], sc1B[tid]);
        sh_w2[tid] = sc2W[tid];
    }
    float b2s = sc2B[0];

    if (tid < TRES) {
        int n = n0 + tid;
        float nx = pn[3 * n], ny = pn[3 * n + 1], nz = pn[3 * n + 2];
        float ax = pca[3 * n], ay = pca[3 * n + 1], az = pca[3 * n + 2];
        float cx = pc[3 * n], cy = pc[3 * n + 1], cz = pc[3 * n + 2];
        float v1x = ax - nx, v1y = ay - ny, v1z = az - nz;
        float d1 = sqrtf(v1x * v1x + v1y * v1y + v1z * v1z);
        float i1 = 1.0f / fmaxf(d1, 1e-8f);
        float f1x = v1x * i1, f1y = v1y * i1, f1z = v1z * i1;
        float v2x = cx - ax, v2y = cy - ay, v2z = cz - az;
        float d2 = sqrtf(v2x * v2x + v2y * v2y + v2z * v2z);
        float i2 = 1.0f / fmaxf(d2, 1e-8f);
        float f2x = v2x * i2, f2y = v2y * i2, f2z = v2z * i2;
        float crx = f1y * f2z - f1z * f2y;
        float cry = f1z * f2x - f1x * f2z;
        float crz = f1x * f2y - f1y * f2x;
        float dc = sqrtf(crx * crx + cry * cry + crz * crz);
        float i3 = 1.0f / fmaxf(dc, 1e-8f);
        float f3x = crx * i3, f3y = cry * i3, f3z = crz * i3;

        int r0 = 2 * tid;
        sh_d[r0] = d1;
        sh_d[r0 + 1] = d2;
        sh_p[r0 * 3 + 0] = v1x * f1x + v1y * f1y + v1z * f1z;
        sh_p[r0 * 3 + 1] = v1x * f2x + v1y * f2y + v1z * f2z;
        sh_p[r0 * 3 + 2] = v1x * f3x + v1y * f3y + v1z * f3z;
        sh_p[(r0 + 1) * 3 + 0] = v2x * f1x + v2y * f1y + v2z * f1z;
        sh_p[(r0 + 1) * 3 + 1] = v2x * f2x + v2y * f2y + v2z * f2z;
        sh_p[(r0 + 1) * 3 + 2] = v2x * f3x + v2y * f3y + v2z * f3z;
        float q0 = f1x + f1y + f1z;
        float q1 = f2x + f2y + f2z;
        float q2 = f3x + f3y + f3z;
        sh_q[r0 * 3 + 0] = q0; sh_q[r0 * 3 + 1] = q1; sh_q[r0 * 3 + 2] = q2;
        sh_q[(r0 + 1) * 3 + 0] = q0; sh_q[(r0 + 1) * 3 + 1] = q1; sh_q[(r0 + 1) * 3 + 2] = q2;
    }
    __syncthreads();

    // ---- rbf, column-major: 4-way row split ----
    {
        int k = tid & 63;
        int rh = tid >> 6;
        float mu = (float)k * (5.0f / 63.0f);
#pragma unroll
        for (int r = rh; r < 32; r += 4) {
            float t = sh_d[r] - mu;
            bufA[k * STRF + r] = __expf(-10.0f * t * t);
        }
    }
    __syncthreads();

    // ---- radial = rbf @ bbW + b ; g = radial*u*v -> bufB ----
    {
        u64 hA[4], hB[4];
        gemm4<64, false>(bufA2, q, bbW, 128, e0, hA, hB);
        float2 bb = *reinterpret_cast<const float2*>(bbB + e0);
#pragma unroll
        for (int jj = 0; jj < 4; jj++) {
            int rp = rpb + jj;
            int n = n0 + rp;
            const float* L = g_lig + (size_t)(3 * n) * EMB;
            float2 u0 = *reinterpret_cast<const float2*>(L + e0);
            float2 u1 = *reinterpret_cast<const float2*>(L + EMB + e0);
            float2 u2 = *reinterpret_cast<const float2*>(L + 2 * EMB + e0);
            float h0, h1;
            up2(hA[jj], h0, h1);
            bufBD[e0 * STRD + rp] = pk2((h0 + bb.x) * u0.x * u1.x, (h1 + bb.x) * u1.x * u2.x);
            up2(hB[jj], h0, h1);
            bufBD[e1 * STRD + rp] = pk2((h0 + bb.y) * u0.y * u1.y, (h1 + bb.y) * u1.y * u2.y);
        }
    }
    __syncthreads();

    // ---- h = g @ e1W ; scalarization + silu-MLP -> s1 in bufA ----
    {
        u64 hA[4], hB[4];
        gemm4<128, false>(bufB2, q, e1W, 128, e0, hA, hB);
        float2 b1c = *reinterpret_cast<const float2*>(e1B + e0);
#pragma unroll 1
        for (int jj = 0; jj < 4; jj++) {
            int rp = rpb + jj;
            int r0 = 2 * rp, r1 = r0 + 1;
            float p00 = sh_p[r0 * 3 + 0], p01 = sh_p[r0 * 3 + 1], p02 = sh_p[r0 * 3 + 2];
            float p10 = sh_p[r1 * 3 + 0], p11 = sh_p[r1 * 3 + 1], p12 = sh_p[r1 * 3 + 2];
            float q0 = sh_q[r0 * 3 + 0], q1 = sh_q[r0 * 3 + 1], q2 = sh_q[r0 * 3 + 2];
            float hA0, hA1, hB0, hB1;
            up2(hA[jj], hA0, hA1);
            up2(hB[jj], hB0, hB1);
            float sA0x = hA0 * p00 + b1c.x * q0, sA0y = hA0 * p01 + b1c.x * q1, sA0z = hA0 * p02 + b1c.x * q2;
            float sA1x = hA1 * p10 + b1c.x * q0, sA1y = hA1 * p11 + b1c.x * q1, sA1z = hA1 * p12 + b1c.x * q2;
            float sB0x = hB0 * p00 + b1c.y * q0, sB0y = hB0 * p01 + b1c.y * q1, sB0z = hB0 * p02 + b1c.y * q2;
            float sB1x = hB1 * p10 + b1c.y * q0, sB1y = hB1 * p11 + b1c.y * q1, sB1z = hB1 * p12 + b1c.y * q2;
            float zA0 = 0.f, zA1 = 0.f, zB0 = 0.f, zB1 = 0.f;
#pragma unroll 1
            for (int m = 0; m < 32; m++) {
                float4 wv = reinterpret_cast<const float4*>(sh_w14)[m];
                float wo = sh_w2[m];
                float t0 = fmaf(sA0x, wv.x, fmaf(sA0y, wv.y, fmaf(sA0z, wv.z, wv.w)));
                float t1 = fmaf(sA1x, wv.x, fmaf(sA1y, wv.y, fmaf(sA1z, wv.z, wv.w)));
                float t2 = fmaf(sB0x, wv.x, fmaf(sB0y, wv.y, fmaf(sB0z, wv.z, wv.w)));
                float t3 = fmaf(sB1x, wv.x, fmaf(sB1y, wv.y, fmaf(sB1z, wv.z, wv.w)));
                zA0 = fmaf(fast_silu(t0), wo, zA0);
                zA1 = fmaf(fast_silu(t1), wo, zA1);
                zB0 = fmaf(fast_silu(t2), wo, zB0);
                zB1 = fmaf(fast_silu(t3), wo, zB1);
            }
            bufAD[e0 * STRD + rp] = pk2(zA0 + b2s + sA0x, zA1 + b2s + sA1x);
            bufAD[e1 * STRD + rp] = pk2(zB0 + b2s + sB0x, zB1 + b2s + sB1x);
        }
    }
    __syncthreads();

    // ---- fused MLP: per 128-ch chunk, m=relu(s1@e2aW)+b in bufB, y += m@e2bW ----
    u64 yA[4], yB[4];
#pragma unroll
    for (int i = 0; i < 4; i++) { yA[i] = 0ull; yB[i] = 0ull; }
#pragma unroll 1
    for (int ch = 0; ch < 2; ch++) {
        u64 mA[4], mB[4];
        gemm4<128, false>(bufA2, q, e2aW + ch * 128, 256, e0, mA, mB);
        float2 ba = *reinterpret_cast<const float2*>(e2aB + ch * 128 + e0);
#pragma unroll
        for (int jj = 0; jj < 4; jj++) {
            int rp = rpb + jj;
            float x0, x1;
            up2(mA[jj], x0, x1);
            bufBD[e0 * STRD + rp] = pk2(fmaxf(x0 + ba.x, 0.f), fmaxf(x1 + ba.x, 0.f));
            up2(mB[jj], x0, x1);
            bufBD[e1 * STRD + rp] = pk2(fmaxf(x0 + ba.y, 0.f), fmaxf(x1 + ba.y, 0.f));
        }
        __syncthreads();
        gemm4<128, true>(bufB2, q, e2bW + ch * 128 * 128, 128, e0, yA, yB);
        __syncthreads();
    }

    // ---- epilogue (float2 stores) ----
    {
        float2 bb2 = *reinterpret_cast<const float2*>(e2bB + e0);
#pragma unroll
        for (int jj = 0; jj < 4; jj++) {
            int rp = rpb + jj;
            int n = n0 + rp;
            int rt = rtype[n];
            float2 re = *reinterpret_cast<const float2*>(resemb + (size_t)rt * EMB + e0);
            float ya0, ya1, yb0, yb1;
            up2(yA[jj], ya0, ya1);
            up2(yB[jj], yb0, yb1);
            float2 r;
            r.x = 0.5f * (ya0 + ya1) + bb2.x + re.x;
            r.y = 0.5f * (yb0 + yb1) + bb2.y + re.y;
            *reinterpret_cast<float2*>(out + (size_t)n * EMB + e0) = r;
        }
    }
}

// ---------------- launch ----------------
extern "C" void kernel_launch(void* const* d_in, const int* in_sizes, int n_in,
                              void* d_out, int out_size) {
    const float* pn    = (const float*)d_in[0];
    const float* pca   = (const float*)d_in[1];
    const float* pc    = (const float*)d_in[2];
    const int*   rtype = (const int*)  d_in[3];
    /* batch d_in[4] unused */
    const int*   eidx  = (const int*)  d_in[5];
    const float* resemb= (const float*)d_in[6];
    const float* bbemb = (const float*)d_in[7];
    const float* ligW  = (const float*)d_in[8];
    const float* ligb  = (const float*)d_in[9];
    const float* bbW   = (const float*)d_in[10];
    const float* bbB   = (const float*)d_in[11];
    const float* e1W   = (const float*)d_in[12];
    const float* e1B   = (const float*)d_in[13];
    const float* e2aW  = (const float*)d_in[14];
    const float* e2aB  = (const float*)d_in[15];
    const float* e2bW  = (const float*)d_in[16];
    const float* e2bB  = (const float*)d_in[17];
    const float* sc1W  = (const float*)d_in[18];
    const float* sc1B  = (const float*)d_in[19];
    const float* sc2W  = (const float*)d_in[20];
    const float* sc2B  = (const float*)d_in[21];
    float* out = (float*)d_out;

    size_t smem_res = SMEM_RES_FLOATS * sizeof(float);
    cudaFuncSetAttribute(k_res, cudaFuncAttributeMaxDynamicSharedMemorySize, (int)smem_res);
    cudaFuncSetAttribute(k_res, cudaFuncAttributePreferredSharedMemoryCarveout, 100);

    k_init<<<256, 256>>>(pn, pca, pc, ligW, ligb, bbemb);
    k_edge<<<NEDGE / 256, 256>>>(eidx);
    k_lig_all<<<NODES / 4, 256>>>(bbemb);
    k_fix<<<592, 256>>>();
    k_res<<<NRES / TRES, 256, smem_res>>>(pn, pca, pc, rtype, resemb,
                                          bbW, bbB, e1W, e1B,
                                          e2aW, e2aB, e2bW, e2bB,
                                          sc1W, sc1B, sc2W, sc2B, out);
}

// round 17
// speedup vs baseline: 1.2230x; 1.0279x over previous
#include <cuda_runtime.h>
#include <math.h>

#define NRES  16384
#define NODES 49152
#define NODESP (NODES + 32)
#define NEDGE 786432
#define EMB   128
#define NRAD  64
#define TRES  16
#define STRF  36   // activation column stride in floats
#define STRD  18   // in u64
#define STRV  9    // in ulonglong2

typedef unsigned long long u64;

__device__ __forceinline__ u64 pk2(float lo, float hi) {
    u64 r; asm("mov.b64 %0,{%1,%2};" : "=l"(r) : "f"(lo), "f"(hi)); return r;
}
__device__ __forceinline__ u64 pkw(float w) {
    u64 r; asm("mov.b64 %0,{%1,%1};" : "=l"(r) : "f"(w)); return r;
}
__device__ __forceinline__ void up2(u64 a, float& lo, float& hi) {
    asm("mov.b64 {%0,%1},%2;" : "=f"(lo), "=f"(hi) : "l"(a));
}
__device__ __forceinline__ u64 ff2(u64 a, u64 b, u64 c) {
    u64 d; asm("fma.rn.f32x2 %0,%1,%2,%3;" : "=l"(d) : "l"(a), "l"(b), "l"(c)); return d;
}
__device__ __forceinline__ float fast_silu(float t) {
    float h = 0.5f * t, th;
    asm("tanh.approx.f32 %0,%1;" : "=f"(th) : "f"(h));
    return fmaf(h, th, h);
}

// ---------------- device scratch ----------------
__device__ float4 g_pos[NODES];
__device__ float  g_cnt[NODESP * 3];
__device__ float  g_lig[(size_t)NODESP * EMB];
__device__ float  g_bp[3 * EMB];
__device__ float  g_Wp[192 * EMB];     // Wp[t*64+k][c] = ligW[k][c]*bbemb[t][c]
__device__ int2   g_elist[NEDGE];      // in-cutoff edge records {(i<<2)|tj, bits(d)}
__device__ int    g_ecnt;

// ---------------- init ----------------
__global__ void __launch_bounds__(256) k_init(const float* __restrict__ pn,
                                              const float* __restrict__ pca,
                                              const float* __restrict__ pc,
                                              const float* __restrict__ ligW,
                                              const float* __restrict__ ligb,
                                              const float* __restrict__ bbemb) {
    int idx = blockIdx.x * blockDim.x + threadIdx.x;
    int stride = gridDim.x * blockDim.x;
    const int n2 = (NODESP * 3) / 4;
    float4 z = make_float4(0.f, 0.f, 0.f, 0.f);
    float4* cvec = reinterpret_cast<float4*>(g_cnt);
    for (int i = idx; i < n2; i += stride) cvec[i] = z;
    if (idx == 0) g_ecnt = 0;

    if (idx < NRES) {
        int n = idx;
        g_pos[3 * n + 0] = make_float4(pn[3 * n], pn[3 * n + 1], pn[3 * n + 2], 0.f);
        g_pos[3 * n + 1] = make_float4(pca[3 * n], pca[3 * n + 1], pca[3 * n + 2], 0.f);
        g_pos[3 * n + 2] = make_float4(pc[3 * n], pc[3 * n + 1], pc[3 * n + 2], 0.f);
    }
    if (idx < 192 * EMB) {
        int c = idx & 127;
        int kk = idx >> 7;
        int t = kk / NRAD;
        int k = kk - t * NRAD;
        g_Wp[idx] = ligW[k * EMB + c] * bbemb[t * EMB + c];
    }
    if (idx < 3 * EMB) g_bp[idx] = ligb[idx & 127] * bbemb[idx];
}

// ---------------- edge phase: count + compact in-cutoff records ----------------
// record only if some rbf bin has |d-mu| <= 1.25 -> d < 6.25, d2 < 39.0625
__global__ void __launch_bounds__(256) k_edge(const int* __restrict__ ei) {
    int e = blockIdx.x * blockDim.x + threadIdx.x;
    if (e >= NEDGE) return;
    int i = ei[e];
    int j = ei[NEDGE + e];
    float4 pi = g_pos[i];
    float4 pj = g_pos[j];
    float dx = pi.x - pj.x, dy = pi.y - pj.y, dz = pi.z - pj.z;
    float d2 = dx * dx + dy * dy + dz * dz;
    int tj = j % 3;
    atomicAdd(&g_cnt[i * 3 + tj], 1.0f);
    if (d2 < 39.0625f) {
        int p = atomicAdd(&g_ecnt, 1);
        g_elist[p] = make_int2((i << 2) | tj, __float_as_int(sqrtf(d2)));
    }
}

// ---------------- closed-form lig for ALL nodes (float4 threads) ----------------
__global__ void __launch_bounds__(256) k_lig_all(const float* __restrict__ bbemb) {
    int idx = blockIdx.x * blockDim.x + threadIdx.x;   // NODES*32 slots
    int n = idx >> 5;
    int e0 = 4 * (idx & 31);
    if (n >= NODES) return;
    float c0 = g_cnt[n * 3 + 0], c1 = g_cnt[n * 3 + 1], c2 = g_cnt[n * 3 + 2];
    float deg = c0 + c1 + c2;
    int a = n % 3;
    float4 xs = *reinterpret_cast<const float4*>(bbemb + a * EMB + e0);
    float4 b0 = *reinterpret_cast<const float4*>(g_bp + e0);
    float4 b1 = *reinterpret_cast<const float4*>(g_bp + EMB + e0);
    float4 b2 = *reinterpret_cast<const float4*>(g_bp + 2 * EMB + e0);
    float4 r;
    r.x = deg * xs.x + c0 * b0.x + c1 * b1.x + c2 * b2.x;
    r.y = deg * xs.y + c0 * b0.y + c1 * b1.y + c2 * b2.y;
    r.z = deg * xs.z + c0 * b0.z + c1 * b1.z + c2 * b2.z;
    r.w = deg * xs.w + c0 * b0.w + c1 * b1.w + c2 * b2.w;
    *reinterpret_cast<float4*>(g_lig + (size_t)n * EMB + e0) = r;
}

// ---------------- per-edge correction: lig[i] += rbf(d) @ Wp[tj], truncated support ----------------
__global__ void __launch_bounds__(256) k_fix() {
    __shared__ float srbf[8][64];
    int wid = threadIdx.x >> 5, lane = threadIdx.x & 31;
    int nwarp = gridDim.x * 8;
    int ecnt = g_ecnt;
    const float step = 5.0f / 63.0f;
    const float inv_step = 63.0f / 5.0f;
    for (int e = blockIdx.x * 8 + wid; e < ecnt; e += nwarp) {
        int2 rec = g_elist[e];
        int i = rec.x >> 2, tj = rec.x & 3;
        float d = __int_as_float(rec.y);
        float t0 = d - (2 * lane) * step;
        float t1 = d - (2 * lane + 1) * step;
        srbf[wid][2 * lane] = __expf(-10.0f * t0 * t0);
        srbf[wid][2 * lane + 1] = __expf(-10.0f * t1 * t1);
        __syncwarp();
        // support: |d - mu_k| <= 1.25 -> dropped terms < 1.6e-7
        int klo = max(0, (int)ceilf((d - 1.25f) * inv_step));
        int khi = min(63, (int)floorf((d + 1.25f) * inv_step));
        const ulonglong2* W = reinterpret_cast<const ulonglong2*>(g_Wp + tj * 64 * EMB + 4 * lane);
        u64 a0 = 0ull, a1 = 0ull;
#pragma unroll 2
        for (int k = klo; k <= khi; k++) {
            float r = srbf[wid][k];
            u64 rp = pkw(r);
            ulonglong2 wv = __ldg(W + k * 32);   // stride 128 floats = 32 ulonglong2
            a0 = ff2(rp, wv.x, a0);
            a1 = ff2(rp, wv.y, a1);
        }
        float v0, v1, v2, v3;
        up2(a0, v0, v1);
        up2(a1, v2, v3);
        unsigned long long gaddr = (unsigned long long)
            __cvta_generic_to_global(g_lig + (size_t)i * EMB + 4 * lane);
        asm volatile("red.global.add.v4.f32 [%0], {%1,%2,%3,%4};"
                     :: "l"(gaddr), "f"(v0), "f"(v1), "f"(v2), "f"(v3) : "memory");
        __syncwarp();
    }
}

// ---------------- FMA2 GEMM: 4 row-pairs, adjacent channel pair (e0, e0+1) ----------------
template<int K, bool ACC>
__device__ __forceinline__ void gemm4(const ulonglong2* __restrict__ X, int q,
                                      const float* __restrict__ W, int ldw,
                                      int e0, u64* aA, u64* aB) {
    if (!ACC) {
#pragma unroll
        for (int i = 0; i < 4; i++) { aA[i] = 0ull; aB[i] = 0ull; }
    }
    const ulonglong2* xp = X + 2 * q;
#pragma unroll 8
    for (int k = 0; k < K; k++) {
        float2 wv = __ldg(reinterpret_cast<const float2*>(W + (size_t)k * ldw + e0));
        u64 w0 = pkw(wv.x);
        u64 w1 = pkw(wv.y);
        ulonglong2 x0 = xp[k * STRV + 0];
        ulonglong2 x1 = xp[k * STRV + 1];
        aA[0] = ff2(x0.x, w0, aA[0]); aA[1] = ff2(x0.y, w0, aA[1]);
        aA[2] = ff2(x1.x, w0, aA[2]); aA[3] = ff2(x1.y, w0, aA[3]);
        aB[0] = ff2(x0.x, w1, aB[0]); aB[1] = ff2(x0.y, w1, aB[1]);
        aB[2] = ff2(x1.x, w1, aB[2]); aB[3] = ff2(x1.y, w1, aB[3]);
    }
}

// ---------------- residue phase (unchanged structure) ----------------
#define SMEM_RES_FLOATS (4608 + 4608 + 96 + 96 + 32 + 128 + 32)

__global__ void __launch_bounds__(256, 4) k_res(
    const float* __restrict__ pn, const float* __restrict__ pca, const float* __restrict__ pc,
    const int* __restrict__ rtype, const float* __restrict__ resemb,
    const float* __restrict__ bbW, const float* __restrict__ bbB,
    const float* __restrict__ e1W, const float* __restrict__ e1B,
    const float* __restrict__ e2aW, const float* __restrict__ e2aB,
    const float* __restrict__ e2bW, const float* __restrict__ e2bB,
    const float* __restrict__ sc1W, const float* __restrict__ sc1B,
    const float* __restrict__ sc2W, const float* __restrict__ sc2B,
    float* __restrict__ out)
{
    extern __shared__ float sm[];
    float* bufA = sm;                      // 4608 (rbf then s1)
    float* bufB = sm + 4608;               // 4608 (g, then m-chunks)
    float* sh_p = sm + 9216;               // 96
    float* sh_q = sh_p + 96;               // 96
    float* sh_d = sh_q + 96;               // 32
    float* sh_w14 = sh_d + 32;             // 128 (float4[32]: w0,w1,w2,b)
    float* sh_w2 = sh_w14 + 128;           // 32
    const ulonglong2* bufA2 = reinterpret_cast<const ulonglong2*>(bufA);
    const ulonglong2* bufB2 = reinterpret_cast<const ulonglong2*>(bufB);
    u64* bufAD = reinterpret_cast<u64*>(bufA);
    u64* bufBD = reinterpret_cast<u64*>(bufB);

    int tid = threadIdx.x;
    int n0 = blockIdx.x * TRES;
    int e0 = 2 * (tid & 63), q = tid >> 6, e1 = e0 + 1;
    int rpb = 4 * q;

    if (tid < 32) {
        reinterpret_cast<float4*>(sh_w14)[tid] =
            make_float4(sc1W[tid], sc1W[32 + tid], sc1W[64 + tid], sc1B[tid]);
        sh_w2[tid] = sc2W[tid];
    }
    float b2s = sc2B[0];

    if (tid < TRES) {
        int n = n0 + tid;
        float nx = pn[3 * n], ny = pn[3 * n + 1], nz = pn[3 * n + 2];
        float ax = pca[3 * n], ay = pca[3 * n + 1], az = pca[3 * n + 2];
        float cx = pc[3 * n], cy = pc[3 * n + 1], cz = pc[3 * n + 2];
        float v1x = ax - nx, v1y = ay - ny, v1z = az - nz;
        float d1 = sqrtf(v1x * v1x + v1y * v1y + v1z * v1z);
        float i1 = 1.0f / fmaxf(d1, 1e-8f);
        float f1x = v1x * i1, f1y = v1y * i1, f1z = v1z * i1;
        float v2x = cx - ax, v2y = cy - ay, v2z = cz - az;
        float d2 = sqrtf(v2x * v2x + v2y * v2y + v2z * v2z);
        float i2 = 1.0f / fmaxf(d2, 1e-8f);
        float f2x = v2x * i2, f2y = v2y * i2, f2z = v2z * i2;
        float crx = f1y * f2z - f1z * f2y;
        float cry = f1z * f2x - f1x * f2z;
        float crz = f1x * f2y - f1y * f2x;
        float dc = sqrtf(crx * crx + cry * cry + crz * crz);
        float i3 = 1.0f / fmaxf(dc, 1e-8f);
        float f3x = crx * i3, f3y = cry * i3, f3z = crz * i3;

        int r0 = 2 * tid;
        sh_d[r0] = d1;
        sh_d[r0 + 1] = d2;
        sh_p[r0 * 3 + 0] = v1x * f1x + v1y * f1y + v1z * f1z;
        sh_p[r0 * 3 + 1] = v1x * f2x + v1y * f2y + v1z * f2z;
        sh_p[r0 * 3 + 2] = v1x * f3x + v1y * f3y + v1z * f3z;
        sh_p[(r0 + 1) * 3 + 0] = v2x * f1x + v2y * f1y + v2z * f1z;
        sh_p[(r0 + 1) * 3 + 1] = v2x * f2x + v2y * f2y + v2z * f2z;
        sh_p[(r0 + 1) * 3 + 2] = v2x * f3x + v2y * f3y + v2z * f3z;
        float q0 = f1x + f1y + f1z;
        float q1 = f2x + f2y + f2z;
        float q2 = f3x + f3y + f3z;
        sh_q[r0 * 3 + 0] = q0; sh_q[r0 * 3 + 1] = q1; sh_q[r0 * 3 + 2] = q2;
        sh_q[(r0 + 1) * 3 + 0] = q0; sh_q[(r0 + 1) * 3 + 1] = q1; sh_q[(r0 + 1) * 3 + 2] = q2;
    }
    __syncthreads();

    // ---- rbf, column-major: 4-way row split ----
    {
        int k = tid & 63;
        int rh = tid >> 6;
        float mu = (float)k * (5.0f / 63.0f);
#pragma unroll
        for (int r = rh; r < 32; r += 4) {
            float t = sh_d[r] - mu;
            bufA[k * STRF + r] = __expf(-10.0f * t * t);
        }
    }
    __syncthreads();

    // ---- radial = rbf @ bbW + b ; g = radial*u*v -> bufB ----
    {
        u64 hA[4], hB[4];
        gemm4<64, false>(bufA2, q, bbW, 128, e0, hA, hB);
        float2 bb = *reinterpret_cast<const float2*>(bbB + e0);
#pragma unroll
        for (int jj = 0; jj < 4; jj++) {
            int rp = rpb + jj;
            int n = n0 + rp;
            const float* L = g_lig + (size_t)(3 * n) * EMB;
            float2 u0 = *reinterpret_cast<const float2*>(L + e0);
            float2 u1 = *reinterpret_cast<const float2*>(L + EMB + e0);
            float2 u2 = *reinterpret_cast<const float2*>(L + 2 * EMB + e0);
            float h0, h1;
            up2(hA[jj], h0, h1);
            bufBD[e0 * STRD + rp] = pk2((h0 + bb.x) * u0.x * u1.x, (h1 + bb.x) * u1.x * u2.x);
            up2(hB[jj], h0, h1);
            bufBD[e1 * STRD + rp] = pk2((h0 + bb.y) * u0.y * u1.y, (h1 + bb.y) * u1.y * u2.y);
        }
    }
    __syncthreads();

    // ---- h = g @ e1W ; scalarization + silu-MLP -> s1 in bufA ----
    {
        u64 hA[4], hB[4];
        gemm4<128, false>(bufB2, q, e1W, 128, e0, hA, hB);
        float2 b1c = *reinterpret_cast<const float2*>(e1B + e0);
#pragma unroll 1
        for (int jj = 0; jj < 4; jj++) {
            int rp = rpb + jj;
            int r0 = 2 * rp, r1 = r0 + 1;
            float p00 = sh_p[r0 * 3 + 0], p01 = sh_p[r0 * 3 + 1], p02 = sh_p[r0 * 3 + 2];
            float p10 = sh_p[r1 * 3 + 0], p11 = sh_p[r1 * 3 + 1], p12 = sh_p[r1 * 3 + 2];
            float q0 = sh_q[r0 * 3 + 0], q1 = sh_q[r0 * 3 + 1], q2 = sh_q[r0 * 3 + 2];
            float hA0, hA1, hB0, hB1;
            up2(hA[jj], hA0, hA1);
            up2(hB[jj], hB0, hB1);
            float sA0x = hA0 * p00 + b1c.x * q0, sA0y = hA0 * p01 + b1c.x * q1, sA0z = hA0 * p02 + b1c.x * q2;
            float sA1x = hA1 * p10 + b1c.x * q0, sA1y = hA1 * p11 + b1c.x * q1, sA1z = hA1 * p12 + b1c.x * q2;
            float sB0x = hB0 * p00 + b1c.y * q0, sB0y = hB0 * p01 + b1c.y * q1, sB0z = hB0 * p02 + b1c.y * q2;
            float sB1x = hB1 * p10 + b1c.y * q0, sB1y = hB1 * p11 + b1c.y * q1, sB1z = hB1 * p12 + b1c.y * q2;
            float zA0 = 0.f, zA1 = 0.f, zB0 = 0.f, zB1 = 0.f;
#pragma unroll 1
            for (int m = 0; m < 32; m++) {
                float4 wv = reinterpret_cast<const float4*>(sh_w14)[m];
                float wo = sh_w2[m];
                float t0 = fmaf(sA0x, wv.x, fmaf(sA0y, wv.y, fmaf(sA0z, wv.z, wv.w)));
                float t1 = fmaf(sA1x, wv.x, fmaf(sA1y, wv.y, fmaf(sA1z, wv.z, wv.w)));
                float t2 = fmaf(sB0x, wv.x, fmaf(sB0y, wv.y, fmaf(sB0z, wv.z, wv.w)));
                float t3 = fmaf(sB1x, wv.x, fmaf(sB1y, wv.y, fmaf(sB1z, wv.z, wv.w)));
                zA0 = fmaf(fast_silu(t0), wo, zA0);
                zA1 = fmaf(fast_silu(t1), wo, zA1);
                zB0 = fmaf(fast_silu(t2), wo, zB0);
                zB1 = fmaf(fast_silu(t3), wo, zB1);
            }
            bufAD[e0 * STRD + rp] = pk2(zA0 + b2s + sA0x, zA1 + b2s + sA1x);
            bufAD[e1 * STRD + rp] = pk2(zB0 + b2s + sB0x, zB1 + b2s + sB1x);
        }
    }
    __syncthreads();

    // ---- fused MLP: per 128-ch chunk, m=relu(s1@e2aW)+b in bufB, y += m@e2bW ----
    u64 yA[4], yB[4];
#pragma unroll
    for (int i = 0; i < 4; i++) { yA[i] = 0ull; yB[i] = 0ull; }
#pragma unroll 1
    for (int ch = 0; ch < 2; ch++) {
        u64 mA[4], mB[4];
        gemm4<128, false>(bufA2, q, e2aW + ch * 128, 256, e0, mA, mB);
        float2 ba = *reinterpret_cast<const float2*>(e2aB + ch * 128 + e0);
#pragma unroll
        for (int jj = 0; jj < 4; jj++) {
            int rp = rpb + jj;
            float x0, x1;
            up2(mA[jj], x0, x1);
            bufBD[e0 * STRD + rp] = pk2(fmaxf(x0 + ba.x, 0.f), fmaxf(x1 + ba.x, 0.f));
            up2(mB[jj], x0, x1);
            bufBD[e1 * STRD + rp] = pk2(fmaxf(x0 + ba.y, 0.f), fmaxf(x1 + ba.y, 0.f));
        }
        __syncthreads();
        gemm4<128, true>(bufB2, q, e2bW + ch * 128 * 128, 128, e0, yA, yB);
        __syncthreads();
    }

    // ---- epilogue (float2 stores) ----
    {
        float2 bb2 = *reinterpret_cast<const float2*>(e2bB + e0);
#pragma unroll
        for (int jj = 0; jj < 4; jj++) {
            int rp = rpb + jj;
            int n = n0 + rp;
            int rt = rtype[n];
            float2 re = *reinterpret_cast<const float2*>(resemb + (size_t)rt * EMB + e0);
            float ya0, ya1, yb0, yb1;
            up2(yA[jj], ya0, ya1);
            up2(yB[jj], yb0, yb1);
            float2 r;
            r.x = 0.5f * (ya0 + ya1) + bb2.x + re.x;
            r.y = 0.5f * (yb0 + yb1) + bb2.y + re.y;
            *reinterpret_cast<float2*>(out + (size_t)n * EMB + e0) = r;
        }
    }
}

// ---------------- launch ----------------
extern "C" void kernel_launch(void* const* d_in, const int* in_sizes, int n_in,
                              void* d_out, int out_size) {
    const float* pn    = (const float*)d_in[0];
    const float* pca   = (const float*)d_in[1];
    const float* pc    = (const float*)d_in[2];
    const int*   rtype = (const int*)  d_in[3];
    /* batch d_in[4] unused */
    const int*   eidx  = (const int*)  d_in[5];
    const float* resemb= (const float*)d_in[6];
    const float* bbemb = (const float*)d_in[7];
    const float* ligW  = (const float*)d_in[8];
    const float* ligb  = (const float*)d_in[9];
    const float* bbW   = (const float*)d_in[10];
    const float* bbB   = (const float*)d_in[11];
    const float* e1W   = (const float*)d_in[12];
    const float* e1B   = (const float*)d_in[13];
    const float* e2aW  = (const float*)d_in[14];
    const float* e2aB  = (const float*)d_in[15];
    const float* e2bW  = (const float*)d_in[16];
    const float* e2bB  = (const float*)d_in[17];
    const float* sc1W  = (const float*)d_in[18];
    const float* sc1B  = (const float*)d_in[19];
    const float* sc2W  = (const float*)d_in[20];
    const float* sc2B  = (const float*)d_in[21];
    float* out = (float*)d_out;

    size_t smem_res = SMEM_RES_FLOATS * sizeof(float);
    cudaFuncSetAttribute(k_res, cudaFuncAttributeMaxDynamicSharedMemorySize, (int)smem_res);
    cudaFuncSetAttribute(k_res, cudaFuncAttributePreferredSharedMemoryCarveout, 100);

    k_init<<<256, 256>>>(pn, pca, pc, ligW, ligb, bbemb);
    k_edge<<<NEDGE / 256, 256>>>(eidx);
    k_lig_all<<<NODES / 8, 256>>>(bbemb);
    k_fix<<<592, 256>>>();
    k_res<<<NRES / TRES, 256, smem_res>>>(pn, pca, pc, rtype, resemb,
                                          bbW, bbB, e1W, e1B,
                                          e2aW, e2aB, e2bW, e2bB,
                                          sc1W, sc1B, sc2W, sc2B, out);
}